// round 12
// baseline (speedup 1.0000x reference)
#include <cuda_runtime.h>
#include <cuda_bf16.h>
#include <cstdint>

#define B_  8
#define T_  2048
#define C_  1024
#define H_  64
#define BT_  (B_ * T_)          // 16384
#define BTH_ (BT_ * H_)         // 1048576

// ---------------- device scratch (no allocations allowed) ----------------
__device__ __nv_bfloat16 g_W3h[192 * 1024];
__device__ __nv_bfloat16 g_W3l[192 * 1024];
// hi/lo bf16 split of projected Q (pre-scaled), Kp, Vp — [B,T,H] row-major
__device__ __nv_bfloat16 g_qh[BTH_], g_ql[BTH_];
__device__ __nv_bfloat16 g_kh[BTH_], g_kl[BTH_];
__device__ __nv_bfloat16 g_vh[BTH_], g_vl[BTH_];

// ================= helpers =================
__device__ __forceinline__ uint32_t smem_u32(const void* p) {
    uint32_t a;
    asm("{ .reg .u64 t; cvta.to.shared.u64 t, %1; cvt.u32.u64 %0, t; }" : "=r"(a) : "l"(p));
    return a;
}
__device__ __forceinline__ float ex2f(float x) {
    float y;
    asm("ex2.approx.ftz.f32 %0, %1;" : "=f"(y) : "f"(x));
    return y;
}
__device__ __forceinline__ uint32_t pack_bf16(__nv_bfloat16 a, __nv_bfloat16 b) {
    __nv_bfloat162 t(a, b);
    return *reinterpret_cast<uint32_t*>(&t);
}
__device__ __forceinline__ void split2(float v0, float v1, uint32_t& h, uint32_t& l) {
    __nv_bfloat16 h0 = __float2bfloat16(v0), h1 = __float2bfloat16(v1);
    float r0 = v0 - __bfloat162float(h0), r1 = v1 - __bfloat162float(h1);
    h = pack_bf16(h0, h1);
    l = pack_bf16(__float2bfloat16(r0), __float2bfloat16(r1));
}
#define LDSM4(r, addr) \
    asm volatile("ldmatrix.sync.aligned.m8n8.x4.shared.b16 {%0,%1,%2,%3}, [%4];" \
                 : "=r"((r)[0]), "=r"((r)[1]), "=r"((r)[2]), "=r"((r)[3]) : "r"(addr))
#define LDSM4T(r, addr) \
    asm volatile("ldmatrix.sync.aligned.m8n8.x4.trans.shared.b16 {%0,%1,%2,%3}, [%4];" \
                 : "=r"((r)[0]), "=r"((r)[1]), "=r"((r)[2]), "=r"((r)[3]) : "r"(addr))
#define MMA16816(c, a, b0, b1) \
    asm volatile("mma.sync.aligned.m16n8k16.row.col.f32.bf16.bf16.f32 " \
                 "{%0,%1,%2,%3}, {%4,%5,%6,%7}, {%8,%9}, {%0,%1,%2,%3};" \
                 : "+f"((c)[0]), "+f"((c)[1]), "+f"((c)[2]), "+f"((c)[3]) \
                 : "r"((a)[0]), "r"((a)[1]), "r"((a)[2]), "r"((a)[3]), "r"(b0), "r"(b1))
#define CP_ASYNC16(dst, src) \
    asm volatile("cp.async.cg.shared.global [%0], [%1], 16;" :: "r"(dst), "l"(src))
#define CP_COMMIT() asm volatile("cp.async.commit_group;")
#define CP_WAIT(n)  asm volatile("cp.async.wait_group %0;" :: "n"(n))

// ---------------- kernel 1: fuse E/F into K/V weights (smem-staged column) ----------------
// Grid 192 (one output row n per block), 256 threads, 4 cols each.
__global__ void combine_w_kernel(const float* __restrict__ Wq, const float* __restrict__ Wk,
                                 const float* __restrict__ Wv, const float* __restrict__ E,
                                 const float* __restrict__ F) {
    __shared__ float col[64];
    const int n = blockIdx.x;
    const int tid = threadIdx.x;
    const int c4 = tid * 4;

    float4 v;
    if (n < 64) {
        v = *(const float4*)(Wq + (size_t)n * 1024 + c4);
    } else {
        const bool isK = (n < 128);
        const int d = isK ? (n - 64) : (n - 128);
        const float* M = isK ? E : F;
        const float* W = isK ? Wk : Wv;
        if (tid < 64) col[tid] = M[tid * 64 + d];
        __syncthreads();
        float4 s = make_float4(0.f, 0.f, 0.f, 0.f);
        #pragma unroll
        for (int h = 0; h < 64; ++h) {
            float e = col[h];
            float4 w = *(const float4*)(W + (size_t)h * 1024 + c4);
            s.x += e * w.x; s.y += e * w.y; s.z += e * w.z; s.w += e * w.w;
        }
        v = s;
    }
    uint32_t h01, l01, h23, l23;
    split2(v.x, v.y, h01, l01);
    split2(v.z, v.w, h23, l23);
    *(uint2*)&g_W3h[(size_t)n * 1024 + c4] = make_uint2(h01, h23);
    *(uint2*)&g_W3l[(size_t)n * 1024 + c4] = make_uint2(l01, l23);
}

// ---------------- kernel 2: merged mma.sync projection GEMM + x register pipeline ----------------
#define ASTRIDE 40
#define PROJ_A_ELEMS (128 * ASTRIDE)
#define PROJ_B_ELEMS (192 * ASTRIDE)
#define PROJ_SMEM_BYTES ((2 * PROJ_A_ELEMS + 2 * PROJ_B_ELEMS) * 2)   // 51200

__global__ __launch_bounds__(256, 1) void proj_mma_kernel(const float* __restrict__ x) {
    extern __shared__ __nv_bfloat16 psm[];
    __nv_bfloat16* Ah = psm;
    __nv_bfloat16* Al = Ah + PROJ_A_ELEMS;
    __nv_bfloat16* Bh = Al + PROJ_A_ELEMS;
    __nv_bfloat16* Bl = Bh + PROJ_B_ELEMS;

    const int tid = threadIdx.x;
    const int lane = tid & 31, w = tid >> 5;
    const int wm = w & 3, wn = w >> 2;
    const int m0 = blockIdx.x * 128;

    float c[3][2][4][4];
    #pragma unroll
    for (int n = 0; n < 3; ++n)
        #pragma unroll
        for (int i = 0; i < 2; ++i)
            #pragma unroll
            for (int j = 0; j < 4; ++j)
                #pragma unroll
                for (int q = 0; q < 4; ++q) c[n][i][j][q] = 0.f;

    const int arow = wm * 32 + (lane & 15);
    const int brow = wn * 32 + (lane & 15);
    const int koff = (lane >> 4) * 8;

    // register pipeline: preload x chunk 0
    const int xrow = tid >> 3, xc4 = (tid & 7) * 4;   // each thread: 4 rows spaced 32
    float4 xr[4];
    #pragma unroll
    for (int u = 0; u < 4; ++u)
        xr[u] = *(const float4*)(x + (size_t)(m0 + xrow + u * 32) * 1024 + xc4);

    for (int kt = 0; kt < 1024; kt += 32) {
        __syncthreads();
        // A tile: convert prefetched registers -> bf16 hi/lo smem
        #pragma unroll
        for (int u = 0; u < 4; ++u) {
            float4 v = xr[u];
            int row = xrow + u * 32;
            __nv_bfloat16 h0 = __float2bfloat16(v.x), h1 = __float2bfloat16(v.y);
            __nv_bfloat16 h2 = __float2bfloat16(v.z), h3 = __float2bfloat16(v.w);
            __nv_bfloat16 l0 = __float2bfloat16(v.x - __bfloat162float(h0));
            __nv_bfloat16 l1 = __float2bfloat16(v.y - __bfloat162float(h1));
            __nv_bfloat16 l2 = __float2bfloat16(v.z - __bfloat162float(h2));
            __nv_bfloat16 l3 = __float2bfloat16(v.w - __bfloat162float(h3));
            *(uint2*)&Ah[row * ASTRIDE + xc4] = make_uint2(pack_bf16(h0, h1), pack_bf16(h2, h3));
            *(uint2*)&Al[row * ASTRIDE + xc4] = make_uint2(pack_bf16(l0, l1), pack_bf16(l2, l3));
        }
        // B tile: 192 weight rows x 32, hi/lo (L2-hot)
        #pragma unroll
        for (int u = 0; u < 3; ++u) {
            int idx = tid + u * 256;
            int row = idx >> 2, c8 = (idx & 3) * 8;
            size_t g = (size_t)row * 1024 + kt + c8;
            *(uint4*)&Bh[row * ASTRIDE + c8] = *(const uint4*)(g_W3h + g);
            *(uint4*)&Bl[row * ASTRIDE + c8] = *(const uint4*)(g_W3l + g);
        }
        __syncthreads();

        // issue next chunk's x loads early — latency hides under the mma section
        if (kt + 32 < 1024) {
            #pragma unroll
            for (int u = 0; u < 4; ++u)
                xr[u] = *(const float4*)(x + (size_t)(m0 + xrow + u * 32) * 1024 + (kt + 32) + xc4);
        }

        #pragma unroll
        for (int p = 0; p < 3; ++p) {
            const __nv_bfloat16* As = (p == 1) ? Al : Ah;
            const __nv_bfloat16* Bs = (p == 2) ? Bl : Bh;
            #pragma unroll
            for (int k16 = 0; k16 < 2; ++k16) {
                uint32_t a[2][4];
                #pragma unroll
                for (int s = 0; s < 2; ++s)
                    LDSM4(a[s], smem_u32(&As[(arow + s * 16) * ASTRIDE + k16 * 16 + koff]));
                #pragma unroll
                for (int nblk = 0; nblk < 3; ++nblk) {
                    uint32_t b[2][4];
                    #pragma unroll
                    for (int s = 0; s < 2; ++s)
                        LDSM4(b[s], smem_u32(&Bs[(nblk * 64 + brow + s * 16) * ASTRIDE + k16 * 16 + koff]));
                    #pragma unroll
                    for (int ms = 0; ms < 2; ++ms)
                        #pragma unroll
                        for (int nb = 0; nb < 4; ++nb)
                            MMA16816(c[nblk][ms][nb], a[ms], b[nb >> 1][nb & 1], b[nb >> 1][(nb & 1) + 2]);
                }
            }
        }
    }

    #pragma unroll
    for (int nblk = 0; nblk < 3; ++nblk) {
        const float scale = (nblk == 0) ? (0.0625f * 1.4426950408889634f) : 1.0f;
        __nv_bfloat16* ph = (nblk == 0) ? g_qh : (nblk == 1 ? g_kh : g_vh);
        __nv_bfloat16* pl = (nblk == 0) ? g_ql : (nblk == 1 ? g_kl : g_vl);
        #pragma unroll
        for (int ms = 0; ms < 2; ++ms) {
            int r0 = m0 + wm * 32 + ms * 16 + (lane >> 2);
            #pragma unroll
            for (int nb = 0; nb < 4; ++nb) {
                int col = wn * 32 + nb * 8 + (lane & 3) * 2;
                uint32_t h, l;
                split2(c[nblk][ms][nb][0] * scale, c[nblk][ms][nb][1] * scale, h, l);
                *(uint32_t*)&ph[(size_t)r0 * 64 + col] = h;
                *(uint32_t*)&pl[(size_t)r0 * 64 + col] = l;
                split2(c[nblk][ms][nb][2] * scale, c[nblk][ms][nb][3] * scale, h, l);
                *(uint32_t*)&ph[(size_t)(r0 + 8) * 64 + col] = h;
                *(uint32_t*)&pl[(size_t)(r0 + 8) * 64 + col] = l;
            }
        }
    }
}

// ---------------- kernel 3: balanced attention, independent per-half softmax ----------------
// CTA = q-tile pair (p, 31-p), 17 key-iters, 8 warps = 4 row-groups x 2 key halves.
// Each half runs a PRIVATE online softmax (no mid-iter exchange/sync); halves are
// merged once per phase in the epilogue: O = O_a*2^(m_a-M) + O_b*2^(m_b-M).
#define QSTRIDE 72
#define TEN_ELEMS (128 * QSTRIDE)
#define STAGE_ELEMS (4 * TEN_ELEMS)
#define BF16_ELEMS (2 * TEN_ELEMS + 2 * STAGE_ELEMS)
#define ORED_STRIDE 66
#define ATTN_SMEM_BYTES (BF16_ELEMS * 2 + 64 * ORED_STRIDE * 4 + 3 * 64 * 4)   // 202,752

__global__ __launch_bounds__(256, 1) void attn_mma_kernel(float* __restrict__ out) {
    extern __shared__ __nv_bfloat16 sb[];
    __nv_bfloat16* Qh = sb;
    __nv_bfloat16* Ql = sb + TEN_ELEMS;
    __nv_bfloat16* Stg = sb + 2 * TEN_ELEMS;          // [2][4][TEN_ELEMS]
    float* Ored = (float*)(sb + BF16_ELEMS);          // [64][ORED_STRIDE]
    float* redm = Ored + 64 * ORED_STRIDE;            // [2][64] running max per half
    float* redl = redm + 2 * 64;                      // [64]    wc=0's scaled l

    const int b = blockIdx.y;
    const int p = blockIdx.x;
    const int tid = threadIdx.x;
    const int lane = tid & 31, w = tid >> 5;
    const int wr = w & 3;
    const int wc = w >> 2;
    const size_t kvbase = (size_t)(b * T_) * H_;
    const int qts[2] = {p, 31 - p};

    #pragma unroll
    for (int u = 0; u < 4; ++u) {
        int idx = tid + u * 256;
        int row = idx >> 3, c8 = (idx & 7) * 8;
        size_t g = ((size_t)(b * T_) + qts[row >> 6] * 64 + (row & 63)) * H_ + c8;
        *(uint4*)&Qh[row * QSTRIDE + c8] = *(const uint4*)(g_qh + g);
        *(uint4*)&Ql[row * QSTRIDE + c8] = *(const uint4*)(g_ql + g);
    }

    const __nv_bfloat16* gsrc[4] = {g_kh, g_kl, g_vh, g_vl};
    auto prefetch = [&](int stg, int kt) {
        __nv_bfloat16* dst = Stg + stg * STAGE_ELEMS;
        size_t base = kvbase + (size_t)kt * 128 * 64;
        #pragma unroll
        for (int t = 0; t < 4; ++t) {
            #pragma unroll
            for (int u = 0; u < 4; ++u) {
                int idx = tid + u * 256;
                int row = idx >> 3, c8 = (idx & 7) * 8;
                CP_ASYNC16(smem_u32(&dst[t * TEN_ELEMS + row * QSTRIDE + c8]),
                           gsrc[t] + base + (size_t)row * 64 + c8);
            }
        }
    };

    prefetch(0, 0);
    CP_COMMIT();

    int sidx = 0;
    const int koff = (lane >> 4) * 8;
    const int r0loc = lane >> 2;
    const int rg = wr * 16 + r0loc;

    #pragma unroll 1
    for (int phase = 0; phase < 2; ++phase) {
        const int qt = qts[phase];
        const int rowg0 = qt * 64;
        const int ntiles = (qt >> 1) + 1;
        const int arow = phase * 64 + wr * 16 + (lane & 15);

        float m0 = -1e30f, m1 = -1e30f, l0 = 0.f, l1 = 0.f;
        float o[8][4];
        #pragma unroll
        for (int i = 0; i < 8; ++i)
            #pragma unroll
            for (int q = 0; q < 4; ++q) o[i][q] = 0.f;

        for (int kt = 0; kt < ntiles; ++kt) {
            if (kt + 1 < ntiles) {
                prefetch(sidx ^ 1, kt + 1);  CP_COMMIT();  CP_WAIT(1);
            } else if (phase == 0) {
                prefetch(sidx ^ 1, 0);       CP_COMMIT();  CP_WAIT(1);
            } else {
                CP_WAIT(0);
            }
            __syncthreads();

            const __nv_bfloat16* Kh = Stg + sidx * STAGE_ELEMS;
            const __nv_bfloat16* Kl = Kh + TEN_ELEMS;
            const __nv_bfloat16* Vh = Kh + 2 * TEN_ELEMS;
            const __nv_bfloat16* Vl = Kh + 3 * TEN_ELEMS;

            // ---- S = Q @ K^T over this warp's 64-key half (hh + lh + hl) ----
            float s[8][4];
            #pragma unroll
            for (int nb = 0; nb < 8; ++nb)
                #pragma unroll
                for (int q = 0; q < 4; ++q) s[nb][q] = 0.f;

            #pragma unroll
            for (int k16 = 0; k16 < 4; ++k16) {
                uint32_t ah[4], al[4];
                LDSM4(ah, smem_u32(&Qh[arow * QSTRIDE + k16 * 16 + koff]));
                LDSM4(al, smem_u32(&Ql[arow * QSTRIDE + k16 * 16 + koff]));
                #pragma unroll
                for (int g = 0; g < 4; ++g) {
                    uint32_t bh[4], bl[4];
                    int krow = wc * 64 + g * 16 + (lane & 15);
                    LDSM4(bh, smem_u32(&Kh[krow * QSTRIDE + k16 * 16 + koff]));
                    LDSM4(bl, smem_u32(&Kl[krow * QSTRIDE + k16 * 16 + koff]));
                    MMA16816(s[2 * g],     ah, bh[0], bh[2]);
                    MMA16816(s[2 * g],     al, bh[0], bh[2]);
                    MMA16816(s[2 * g],     ah, bl[0], bl[2]);
                    MMA16816(s[2 * g + 1], ah, bh[1], bh[3]);
                    MMA16816(s[2 * g + 1], al, bh[1], bh[3]);
                    MMA16816(s[2 * g + 1], ah, bl[1], bl[3]);
                }
            }

            // ---- causal mask (diagonal iter only) ----
            if (kt == ntiles - 1) {
                int ig0 = rowg0 + rg;
                #pragma unroll
                for (int nb = 0; nb < 8; ++nb) {
                    int cg = kt * 128 + wc * 64 + nb * 8 + (lane & 3) * 2;
                    if (cg > ig0)         s[nb][0] = -1e30f;
                    if (cg + 1 > ig0)     s[nb][1] = -1e30f;
                    if (cg > ig0 + 8)     s[nb][2] = -1e30f;
                    if (cg + 1 > ig0 + 8) s[nb][3] = -1e30f;
                }
            }

            // ---- private online softmax for this key half (no cross-half sync) ----
            float mx0 = -1e30f, mx1 = -1e30f;
            #pragma unroll
            for (int nb = 0; nb < 8; ++nb) {
                mx0 = fmaxf(mx0, fmaxf(s[nb][0], s[nb][1]));
                mx1 = fmaxf(mx1, fmaxf(s[nb][2], s[nb][3]));
            }
            mx0 = fmaxf(mx0, __shfl_xor_sync(0xffffffffu, mx0, 1));
            mx0 = fmaxf(mx0, __shfl_xor_sync(0xffffffffu, mx0, 2));
            mx1 = fmaxf(mx1, __shfl_xor_sync(0xffffffffu, mx1, 1));
            mx1 = fmaxf(mx1, __shfl_xor_sync(0xffffffffu, mx1, 2));

            float mn0 = fmaxf(m0, mx0), mn1 = fmaxf(m1, mx1);
            float al0 = ex2f(m0 - mn0), al1 = ex2f(m1 - mn1);
            m0 = mn0; m1 = mn1;
            #pragma unroll
            for (int i = 0; i < 8; ++i) {
                o[i][0] *= al0; o[i][1] *= al0;
                o[i][2] *= al1; o[i][3] *= al1;
            }
            float rs0 = 0.f, rs1 = 0.f;
            #pragma unroll
            for (int nb = 0; nb < 8; ++nb) {
                float p0 = ex2f(s[nb][0] - mn0); s[nb][0] = p0; rs0 += p0;
                float p1 = ex2f(s[nb][1] - mn0); s[nb][1] = p1; rs0 += p1;
                float p2 = ex2f(s[nb][2] - mn1); s[nb][2] = p2; rs1 += p2;
                float p3 = ex2f(s[nb][3] - mn1); s[nb][3] = p3; rs1 += p3;
            }
            rs0 += __shfl_xor_sync(0xffffffffu, rs0, 1);
            rs0 += __shfl_xor_sync(0xffffffffu, rs0, 2);
            rs1 += __shfl_xor_sync(0xffffffffu, rs1, 1);
            rs1 += __shfl_xor_sync(0xffffffffu, rs1, 2);
            l0 = l0 * al0 + rs0;
            l1 = l1 * al1 + rs1;

            // ---- O += P @ V over this warp's 64-key half ----
            #pragma unroll
            for (int kb = 0; kb < 4; ++kb) {
                uint32_t ph[4], pl[4];
                split2(s[2 * kb][0],     s[2 * kb][1],     ph[0], pl[0]);
                split2(s[2 * kb][2],     s[2 * kb][3],     ph[1], pl[1]);
                split2(s[2 * kb + 1][0], s[2 * kb + 1][1], ph[2], pl[2]);
                split2(s[2 * kb + 1][2], s[2 * kb + 1][3], ph[3], pl[3]);
                #pragma unroll
                for (int g = 0; g < 4; ++g) {
                    uint32_t bh[4], bl[4];
                    int vrow = wc * 64 + kb * 16 + (lane & 15);
                    LDSM4T(bh, smem_u32(&Vh[vrow * QSTRIDE + g * 16 + koff]));
                    LDSM4T(bl, smem_u32(&Vl[vrow * QSTRIDE + g * 16 + koff]));
                    MMA16816(o[2 * g],     ph, bh[0], bh[1]);
                    MMA16816(o[2 * g],     pl, bh[0], bh[1]);
                    MMA16816(o[2 * g],     ph, bl[0], bl[1]);
                    MMA16816(o[2 * g + 1], ph, bh[2], bh[3]);
                    MMA16816(o[2 * g + 1], pl, bh[2], bh[3]);
                    MMA16816(o[2 * g + 1], ph, bl[2], bl[3]);
                }
            }
            sidx ^= 1;
            __syncthreads();    // stage consumed before overwrite
        }

        // ---- phase epilogue: merge the two key halves ----
        if ((lane & 3) == 0) {
            redm[wc * 64 + rg]     = m0;
            redm[wc * 64 + rg + 8] = m1;
        }
        __syncthreads();
        {
            float mo0 = redm[(wc ^ 1) * 64 + rg];
            float mo1 = redm[(wc ^ 1) * 64 + rg + 8];
            float M0 = fmaxf(m0, mo0), M1 = fmaxf(m1, mo1);
            float sc0 = ex2f(m0 - M0), sc1 = ex2f(m1 - M1);
            l0 *= sc0; l1 *= sc1;
            #pragma unroll
            for (int i = 0; i < 8; ++i) {
                o[i][0] *= sc0; o[i][1] *= sc0;
                o[i][2] *= sc1; o[i][3] *= sc1;
            }
        }
        if (wc == 0) {
            if ((lane & 3) == 0) { redl[rg] = l0; redl[rg + 8] = l1; }
            #pragma unroll
            for (int nbo = 0; nbo < 8; ++nbo) {
                int col = nbo * 8 + (lane & 3) * 2;
                *(float2*)&Ored[rg * ORED_STRIDE + col]       = make_float2(o[nbo][0], o[nbo][1]);
                *(float2*)&Ored[(rg + 8) * ORED_STRIDE + col] = make_float2(o[nbo][2], o[nbo][3]);
            }
        }
        __syncthreads();
        if (wc == 1) {
            float inv0 = 1.0f / (l0 + redl[rg]);
            float inv1 = 1.0f / (l1 + redl[rg + 8]);
            float* op0 = out + ((size_t)(b * T_) + rowg0 + rg) * 64;
            float* op1 = op0 + 8 * 64;
            #pragma unroll
            for (int nbo = 0; nbo < 8; ++nbo) {
                int col = nbo * 8 + (lane & 3) * 2;
                float2 a0 = *(float2*)&Ored[rg * ORED_STRIDE + col];
                float2 a1 = *(float2*)&Ored[(rg + 8) * ORED_STRIDE + col];
                *(float2*)(op0 + col) = make_float2((a0.x + o[nbo][0]) * inv0,
                                                    (a0.y + o[nbo][1]) * inv0);
                *(float2*)(op1 + col) = make_float2((a1.x + o[nbo][2]) * inv1,
                                                    (a1.y + o[nbo][3]) * inv1);
            }
        }
        __syncthreads();        // redm/redl/Ored reuse by next phase
    }
}

// ---------------- launch ----------------
extern "C" void kernel_launch(void* const* d_in, const int* in_sizes, int n_in,
                              void* d_out, int out_size) {
    const float* x  = (const float*)d_in[0];
    const float* Wq = (const float*)d_in[1];
    const float* Wk = (const float*)d_in[2];
    const float* Wv = (const float*)d_in[3];
    const float* E  = (const float*)d_in[4];
    const float* F  = (const float*)d_in[5];
    float* out = (float*)d_out;

    combine_w_kernel<<<192, 256>>>(Wq, Wk, Wv, E, F);

    cudaFuncSetAttribute(proj_mma_kernel, cudaFuncAttributeMaxDynamicSharedMemorySize, PROJ_SMEM_BYTES);
    proj_mma_kernel<<<BT_ / 128, 256, PROJ_SMEM_BYTES>>>(x);

    cudaFuncSetAttribute(attn_mma_kernel, cudaFuncAttributeMaxDynamicSharedMemorySize, ATTN_SMEM_BYTES);
    attn_mma_kernel<<<dim3(16, B_), 256, ATTN_SMEM_BYTES>>>(out);
}